// round 7
// baseline (speedup 1.0000x reference)
#include <cuda_runtime.h>
#include <stdint.h>

#define NB   16
#define KMAX 50
#define NG   76
#define GG   (NG*NG)      // 5776
#define NA   3
#define NCLS 80
#define NCH  85
#define CELLS (NA*GG)     // 17328
#define CPT  2
#define BLK  256
#define CPB  (BLK*CPT)    // 512
#define GROUPS (CELLS/CPT)            // 8664
#define NBLK ((GROUPS + BLK - 1)/BLK) // 34
#define TOTB (NB*NBLK)                // 544

__device__ double g_partial[TOTB];
__device__ int    g_count;

// bce(sigmoid(x), t) = softplus(x) - t*x   (clamp inactive for |x|<16)
__device__ __forceinline__ float splus(float x) {
    return __logf(1.0f + __expf(x));
}
__device__ __forceinline__ float sigm(float x) {
    return __fdividef(1.0f, 1.0f + __expf(-x));
}

__global__ void __launch_bounds__(BLK)
fused_kernel(const float* __restrict__ raw,
             const float* __restrict__ labels,
             const float* __restrict__ anchors_all,
             const int*   __restrict__ aidx,
             const int*   __restrict__ imgp,
             float*       __restrict__ out) {
    __shared__ float4   s_box[KMAX];
    __shared__ float    s_thr[KMAX];     // 0.375*area_g
    __shared__ int      s_cell[KMAX];
    __shared__ float    s_t[KMAX][5];    // t0..t3, w2
    __shared__ int      s_cls[KMAX];
    __shared__ float    s_awn[NA], s_ahn[NA];
    __shared__ unsigned s_bits[CPB/32];
    __shared__ int      s_cnt;
    __shared__ double   s_wsum[BLK/32];
    __shared__ int      s_last;

    const int b = blockIdx.y;
    const int t = threadIdx.x;
    const int lane = t & 31, wid = t >> 5;

    // ---------------- prep ---------------------------------------------------
    if (t == 0) s_cnt = 0;
    if (t < CPB/32) s_bits[t] = 0u;
    float img = (float)(*imgp);
    if (t < NA) {
        int ai = aidx[t];
        s_awn[t] = __fdividef(anchors_all[2*ai],     img);
        s_ahn[t] = __fdividef(anchors_all[2*ai + 1], img);
    }
    float lab[5];
    if (t < KMAX) {
        float s = 0.f;
        #pragma unroll
        for (int j = 0; j < 5; j++) { lab[j] = labels[(b*KMAX + t)*5 + j]; s += lab[j]; }
        if (s > 0.f) atomicAdd(&s_cnt, 1);
    }
    __syncthreads();
    const int nlabel = s_cnt;

    if (t < KMAX) {
        bool valid_k = (t < nlabel);
        float tx = lab[1] * (float)NG, ty = lab[2] * (float)NG;
        float tw = lab[3],             th = lab[4];

        int best_all = 0; float best = -1.0f;
        #pragma unroll
        for (int a = 0; a < 9; a++) {
            float aw = __fdividef(anchors_all[2*a], img);
            float ah = __fdividef(anchors_all[2*a+1], img);
            float inter = fminf(tw, aw) * fminf(th, ah);
            float uni   = tw*th + aw*ah - inter;
            float iou   = __fdividef(inter, fmaxf(uni, 1e-16f));
            if (iou > best) { best = iou; best_all = a; }
        }
        bool va = false;
        #pragma unroll
        for (int j = 0; j < NA; j++) va = va || (best_all == aidx[j]);
        int  best_n = best_all % NA;
        int  ti = (int)tx, tj = (int)ty;
        bool valid = valid_k && va && ti >= 0 && ti < NG && tj >= 0 && tj < NG;

        int   cell = -1;
        float t0=0.f,t1=0.f,t2=0.f,t3=0.f,w2=0.f;
        if (valid) {
            cell = (best_n * NG + tj) * NG + ti;
            t0 = tx - floorf(tx);
            t1 = ty - floorf(ty);
            t2 = __logf(__fdividef(tw, s_awn[best_n]) + 1e-16f);
            t3 = __logf(__fdividef(th, s_ahn[best_n]) + 1e-16f);
            w2 = 2.0f - tw * th;
            int local = cell - blockIdx.x * CPB;
            if (local >= 0 && local < CPB)
                atomicOr(&s_bits[local >> 5], 1u << (local & 31));
        }
        float gx=0.f,gy=0.f,gw=0.f,gh=0.f;
        if (valid_k) { gx = tx * (1.0f/(float)NG); gy = ty * (1.0f/(float)NG); gw = tw; gh = th; }

        s_box[t]  = make_float4(gx - gw*0.5f, gy - gh*0.5f, gx + gw*0.5f, gy + gh*0.5f);
        s_thr[t]  = 0.375f * gw * gh;
        s_cell[t] = cell;
        s_t[t][0]=t0; s_t[t][1]=t1; s_t[t][2]=t2; s_t[t][3]=t3; s_t[t][4]=w2;
        s_cls[t]  = (int)lab[0];
    }
    __syncthreads();

    double d = 0.0;

    // ---------------- warp-cooperative obj losses (xy, wh, classes) ---------
    {
        unsigned w0 = s_bits[wid*2], w1 = s_bits[wid*2 + 1];
        unsigned long long m = (unsigned long long)w0 | ((unsigned long long)w1 << 32);
        while (m) {
            int bit = __ffsll((long long)m) - 1;
            m &= m - 1ull;
            int cellg = blockIdx.x * CPB + wid * 64 + bit;
            int a  = cellg / GG;
            int r  = cellg - a * GG;
            int gy = r / NG, gx = r - gy * NG;

            int winner = 0;
            int b0 = 0, b1 = 0, b2 = 0;
            for (int k = 0; k < nlabel; k++) {
                if (s_cell[k] == cellg) {
                    winner = k;                       // last writer wins
                    int cc = s_cls[k];
                    b0 |= (cc == lane);
                    b1 |= (cc == lane + 32);
                    b2 |= (cc == lane + 64);
                }
            }

            const float* base = raw + ((size_t)((b*NA + a)*NCH))*GG + gy*NG + gx;

            float x0 = base[(5 + lane)      * GG];
            float x1 = base[(5 + lane + 32) * GG];
            float x2 = (lane < 16) ? base[(5 + lane + 64) * GG] : 0.0f;
            float cls_sum = (splus(x0) - (float)b0 * x0)
                          + (splus(x1) - (float)b1 * x1);
            if (lane < 16) cls_sum += splus(x2) - (float)b2 * x2;
            #pragma unroll
            for (int o = 16; o > 0; o >>= 1)
                cls_sum += __shfl_xor_sync(0xffffffffu, cls_sum, o);

            if (lane == 0) {
                float rx = base[0];
                float ry = base[1*GG];
                float rw = base[2*GG];
                float rh = base[3*GG];
                float t0 = s_t[winner][0], t1 = s_t[winner][1];
                float t2 = s_t[winner][2], t3 = s_t[winner][3];
                float w2 = s_t[winner][4];
                float lxy = (splus(rx) - t0*rx) + (splus(ry) - t1*ry);
                float dw = rw - t2, dh = rh - t3;
                d += (double)(cls_sum + w2 * (lxy + 0.5f*(dw*dw + dh*dh)));
            }
        }
    }

    // ---------------- main: screened ignore test + conf loss -----------------
    const int gidx = blockIdx.x * BLK + t;
    const bool active = (gidx < GROUPS);
    float RC[CPT];
    float X1[CPT], Y1[CPT], X2[CPT], Y2[CPT], AP[CPT], MD[CPT];
    {
        const int cell0 = gidx * CPT;
        int a  = cell0 / GG;
        int r  = cell0 - a * GG;
        int gy = r / NG, gx0 = r - gy * NG;

        if (active) {
            const float* base = raw + ((size_t)((b*NA + a)*NCH))*GG + gy*NG + gx0;
            float2 vx = *(const float2*)(base + 0*GG);
            float2 vy = *(const float2*)(base + 1*GG);
            float2 vw = *(const float2*)(base + 2*GG);
            float2 vh = *(const float2*)(base + 3*GG);
            float2 vc = *(const float2*)(base + 4*GG);
            RC[0] = vc.x; RC[1] = vc.y;
            float RX[CPT] = {vx.x, vx.y};
            float RY[CPT] = {vy.x, vy.y};
            float RW[CPT] = {vw.x, vw.y};
            float RH[CPT] = {vh.x, vh.y};
            const float awn = s_awn[a], ahn = s_ahn[a];
            const float inv = 1.0f / (float)NG;
            #pragma unroll
            for (int c = 0; c < CPT; c++) {
                float px = (sigm(RX[c]) + (float)(gx0 + c)) * inv;
                float py = (sigm(RY[c]) + (float)gy) * inv;
                float pw = fminf(__expf(RW[c]) * awn, 1.0f);
                float ph = fminf(__expf(RH[c]) * ahn, 1.0f);
                X1[c] = px - pw*0.5f; Y1[c] = py - ph*0.5f;
                X2[c] = px + pw*0.5f; Y2[c] = py + ph*0.5f;
                AP[c] = 0.375f * pw * ph;
                MD[c] = -1e30f;
            }
        } else {
            #pragma unroll
            for (int c = 0; c < CPT; c++) {
                X1[c] = 1e30f; Y1[c] = 1e30f; X2[c] = -1e30f; Y2[c] = -1e30f;
                AP[c] = 0.f; MD[c] = -1e30f; RC[c] = 0.f;
            }
        }
    }

    // warp-wide conservative bbox
    float wx1 = fminf(X1[0], X1[1]), wy1 = fminf(Y1[0], Y1[1]);
    float wx2 = fmaxf(X2[0], X2[1]), wy2 = fmaxf(Y2[0], Y2[1]);
    #pragma unroll
    for (int o = 16; o > 0; o >>= 1) {
        wx1 = fminf(wx1, __shfl_xor_sync(0xffffffffu, wx1, o));
        wy1 = fminf(wy1, __shfl_xor_sync(0xffffffffu, wy1, o));
        wx2 = fmaxf(wx2, __shfl_xor_sync(0xffffffffu, wx2, o));
        wy2 = fmaxf(wy2, __shfl_xor_sync(0xffffffffu, wy2, o));
    }

    // per-lane label screen -> warp-uniform survivor masks
    unsigned msk_lo = (nlabel >= 32) ? 0xffffffffu : ((1u << nlabel) - 1u);
    unsigned msk_hi = (nlabel > 32)  ? ((1u << (nlabel - 32)) - 1u) : 0u;
    bool p0, p1;
    {
        float4 g0 = s_box[lane];
        p0 = (g0.x < wx2) & (g0.z > wx1) & (g0.y < wy2) & (g0.w > wy1);
        int k1 = lane + 32;
        p1 = false;
        if (k1 < KMAX) {
            float4 g1 = s_box[k1];
            p1 = (g1.x < wx2) & (g1.z > wx1) & (g1.y < wy2) & (g1.w > wy1);
        }
    }
    unsigned m0 = __ballot_sync(0xffffffffu, p0) & msk_lo;
    unsigned m1 = __ballot_sync(0xffffffffu, p1) & msk_hi;

    // survivors only
    while (m0) {
        int k = __ffs(m0) - 1; m0 &= m0 - 1u;
        const float4 gb = s_box[k];
        const float  th = s_thr[k];
        #pragma unroll
        for (int c = 0; c < CPT; c++) {
            float iw = fminf(X2[c], gb.z) - fmaxf(X1[c], gb.x);
            float ih = fminf(Y2[c], gb.w) - fmaxf(Y1[c], gb.y);
            float inter = fmaxf(iw, 0.f) * fmaxf(ih, 0.f);
            MD[c] = fmaxf(MD[c], inter - th);
        }
    }
    while (m1) {
        int k = __ffs(m1) + 31; m1 &= m1 - 1u;
        const float4 gb = s_box[k];
        const float  th = s_thr[k];
        #pragma unroll
        for (int c = 0; c < CPT; c++) {
            float iw = fminf(X2[c], gb.z) - fmaxf(X1[c], gb.x);
            float ih = fminf(Y2[c], gb.w) - fmaxf(Y1[c], gb.y);
            float inter = fmaxf(iw, 0.f) * fmaxf(ih, 0.f);
            MD[c] = fmaxf(MD[c], inter - th);
        }
    }

    if (active) {
        #pragma unroll
        for (int c = 0; c < CPT; c++) {
            bool ign = MD[c] > AP[c];
            int  local = t * CPT + c;
            bool obj = (s_bits[local >> 5] >> (local & 31)) & 1u;
            if ((!ign) || obj)
                d += (double)(splus(RC[c]) - (obj ? RC[c] : 0.0f));
        }
    }

    // ---------------- block reduction (deterministic) ------------------------
    #pragma unroll
    for (int o = 16; o > 0; o >>= 1) d += __shfl_down_sync(0xffffffffu, d, o);
    if (lane == 0) s_wsum[wid] = d;
    __syncthreads();
    if (t == 0) {
        double s = 0.0;
        #pragma unroll
        for (int w = 0; w < BLK/32; w++) s += s_wsum[w];
        g_partial[blockIdx.y * gridDim.x + blockIdx.x] = s;
        __threadfence();
        int c = atomicAdd(&g_count, 1);
        s_last = (c == TOTB - 1);
    }
    __syncthreads();

    // ---------------- last block: final reduction ----------------------------
    if (s_last) {
        __shared__ double sh[BLK];
        double s = 0.0;
        for (int i = t; i < TOTB; i += BLK) s += g_partial[i];
        sh[t] = s;
        __syncthreads();
        for (int o = BLK/2; o > 0; o >>= 1) {
            if (t < o) sh[t] += sh[t + o];
            __syncthreads();
        }
        if (t == 0) { out[0] = (float)sh[0]; g_count = 0; }
    }
}

extern "C" void kernel_launch(void* const* d_in, const int* in_sizes, int n_in,
                              void* d_out, int out_size) {
    const float* raw     = (const float*)d_in[0];
    const float* labels  = (const float*)d_in[1];
    const float* anchors = (const float*)d_in[2];
    const int*   aidx    = (const int*)d_in[3];
    const int*   imgp    = (const int*)d_in[4];

    dim3 grid(NBLK, NB);
    fused_kernel<<<grid, BLK>>>(raw, labels, anchors, aidx, imgp, (float*)d_out);
}

// round 12
// speedup vs baseline: 1.5140x; 1.5140x over previous
#include <cuda_runtime.h>
#include <stdint.h>

#define NB   16
#define KMAX 50
#define NG   76
#define GG   (NG*NG)      // 5776
#define NA   3
#define NCLS 80
#define NCH  85
#define CELLS (NA*GG)     // 17328
#define BLK  256
#define CPB  BLK          // 256 cells per block (CPT=1)
#define NBLK ((CELLS + BLK - 1)/BLK)  // 68
#define TOTB (NB*NBLK)                // 1088

__device__ double g_partial[TOTB];
__device__ int    g_count;

// bce(sigmoid(x), t) = softplus(x) - t*x   (clamp inactive for |x|<16)
__device__ __forceinline__ float splus(float x) {
    return __logf(1.0f + __expf(x));
}
__device__ __forceinline__ float sigm(float x) {
    return __fdividef(1.0f, 1.0f + __expf(-x));
}

__global__ void __launch_bounds__(BLK)
fused_kernel(const float* __restrict__ raw,
             const float* __restrict__ labels,
             const float* __restrict__ anchors_all,
             const int*   __restrict__ aidx,
             const int*   __restrict__ imgp,
             float*       __restrict__ out) {
    __shared__ float4   s_box[KMAX];
    __shared__ float    s_thr[KMAX];     // 0.375*area_g
    __shared__ int      s_cell[KMAX];
    __shared__ float    s_t[KMAX][5];    // t0..t3, w2
    __shared__ int      s_cls[KMAX];
    __shared__ float    s_awn[NA], s_ahn[NA];
    __shared__ unsigned s_bits[CPB/32];  // 8 words
    __shared__ int      s_cnt;
    __shared__ double   s_wsum[BLK/32];
    __shared__ int      s_last;

    const int b = blockIdx.y;
    const int t = threadIdx.x;
    const int lane = t & 31, wid = t >> 5;

    // ---------------- prep ---------------------------------------------------
    if (t == 0) s_cnt = 0;
    if (t < CPB/32) s_bits[t] = 0u;
    float img = (float)(*imgp);
    if (t < NA) {
        int ai = aidx[t];
        s_awn[t] = __fdividef(anchors_all[2*ai],     img);
        s_ahn[t] = __fdividef(anchors_all[2*ai + 1], img);
    }
    float lab[5];
    if (t < KMAX) {
        float s = 0.f;
        #pragma unroll
        for (int j = 0; j < 5; j++) { lab[j] = labels[(b*KMAX + t)*5 + j]; s += lab[j]; }
        if (s > 0.f) atomicAdd(&s_cnt, 1);
    }
    __syncthreads();
    const int nlabel = s_cnt;

    if (t < KMAX) {
        bool valid_k = (t < nlabel);
        float tx = lab[1] * (float)NG, ty = lab[2] * (float)NG;
        float tw = lab[3],             th = lab[4];

        int best_all = 0; float best = -1.0f;
        #pragma unroll
        for (int a = 0; a < 9; a++) {
            float aw = __fdividef(anchors_all[2*a], img);
            float ah = __fdividef(anchors_all[2*a+1], img);
            float inter = fminf(tw, aw) * fminf(th, ah);
            float uni   = tw*th + aw*ah - inter;
            float iou   = __fdividef(inter, fmaxf(uni, 1e-16f));
            if (iou > best) { best = iou; best_all = a; }
        }
        bool va = false;
        #pragma unroll
        for (int j = 0; j < NA; j++) va = va || (best_all == aidx[j]);
        int  best_n = best_all % NA;
        int  ti = (int)tx, tj = (int)ty;
        bool valid = valid_k && va && ti >= 0 && ti < NG && tj >= 0 && tj < NG;

        int   cell = -1;
        float t0=0.f,t1=0.f,t2=0.f,t3=0.f,w2=0.f;
        if (valid) {
            cell = (best_n * NG + tj) * NG + ti;
            t0 = tx - floorf(tx);
            t1 = ty - floorf(ty);
            t2 = __logf(__fdividef(tw, s_awn[best_n]) + 1e-16f);
            t3 = __logf(__fdividef(th, s_ahn[best_n]) + 1e-16f);
            w2 = 2.0f - tw * th;
            int local = cell - blockIdx.x * CPB;
            if (local >= 0 && local < CPB)
                atomicOr(&s_bits[local >> 5], 1u << (local & 31));
        }
        float gx=0.f,gy=0.f,gw=0.f,gh=0.f;
        if (valid_k) { gx = tx * (1.0f/(float)NG); gy = ty * (1.0f/(float)NG); gw = tw; gh = th; }

        s_box[t]  = make_float4(gx - gw*0.5f, gy - gh*0.5f, gx + gw*0.5f, gy + gh*0.5f);
        s_thr[t]  = 0.375f * gw * gh;
        s_cell[t] = cell;
        s_t[t][0]=t0; s_t[t][1]=t1; s_t[t][2]=t2; s_t[t][3]=t3; s_t[t][4]=w2;
        s_cls[t]  = (int)lab[0];
    }
    __syncthreads();

    float  f = 0.0f;     // per-thread float accumulator (hot path)
    double d = 0.0;      // obj-epilogue adds (nonzero only at lane 0)

    // ---------------- warp-cooperative obj losses (xy, wh, classes) ---------
    {
        unsigned m = s_bits[wid];
        while (m) {
            int bit = __ffs(m) - 1;
            m &= m - 1u;
            int cellg = blockIdx.x * CPB + wid * 32 + bit;
            int a  = cellg / GG;
            int r  = cellg - a * GG;
            int gy = r / NG, gx = r - gy * NG;

            int winner = 0;
            int b0 = 0, b1 = 0, b2 = 0;
            for (int k = 0; k < nlabel; k++) {
                if (s_cell[k] == cellg) {
                    winner = k;                       // last writer wins
                    int cc = s_cls[k];
                    b0 |= (cc == lane);
                    b1 |= (cc == lane + 32);
                    b2 |= (cc == lane + 64);
                }
            }

            const float* base = raw + ((size_t)((b*NA + a)*NCH))*GG + gy*NG + gx;

            float x0 = base[(5 + lane)      * GG];
            float x1 = base[(5 + lane + 32) * GG];
            float x2 = (lane < 16) ? base[(5 + lane + 64) * GG] : 0.0f;
            float cls_sum = (splus(x0) - (float)b0 * x0)
                          + (splus(x1) - (float)b1 * x1);
            if (lane < 16) cls_sum += splus(x2) - (float)b2 * x2;
            #pragma unroll
            for (int o = 16; o > 0; o >>= 1)
                cls_sum += __shfl_xor_sync(0xffffffffu, cls_sum, o);

            if (lane == 0) {
                float rx = base[0];
                float ry = base[1*GG];
                float rw = base[2*GG];
                float rh = base[3*GG];
                float t0 = s_t[winner][0], t1 = s_t[winner][1];
                float t2 = s_t[winner][2], t3 = s_t[winner][3];
                float w2 = s_t[winner][4];
                float lxy = (splus(rx) - t0*rx) + (splus(ry) - t1*ry);
                float dw = rw - t2, dh = rh - t3;
                d += (double)(cls_sum + w2 * (lxy + 0.5f*(dw*dw + dh*dh)));
            }
        }
    }

    // ---------------- main: screened ignore test + conf loss -----------------
    const int idx = blockIdx.x * BLK + t;
    const bool active = (idx < CELLS);
    float RC = 0.f, X1, Y1, X2, Y2, AP = 0.f, MD = -1e30f;
    {
        int a  = idx / GG;
        int r  = idx - a * GG;
        int gy = r / NG, gx = r - gy * NG;

        if (active) {
            const float* base = raw + ((size_t)((b*NA + a)*NCH))*GG + gy*NG + gx;
            float rx = base[0*GG];
            float ry = base[1*GG];
            float rw = base[2*GG];
            float rh = base[3*GG];
            RC       = base[4*GG];
            const float inv = 1.0f / (float)NG;
            float px = (sigm(rx) + (float)gx) * inv;
            float py = (sigm(ry) + (float)gy) * inv;
            float pw = fminf(__expf(rw) * s_awn[a], 1.0f);
            float ph = fminf(__expf(rh) * s_ahn[a], 1.0f);
            X1 = px - pw*0.5f; Y1 = py - ph*0.5f;
            X2 = px + pw*0.5f; Y2 = py + ph*0.5f;
            AP = 0.375f * pw * ph;
        } else {
            X1 = 1e30f; Y1 = 1e30f; X2 = -1e30f; Y2 = -1e30f;
        }
    }

    // warp-wide conservative bbox (32 adjacent cells)
    float wx1 = X1, wy1 = Y1, wx2 = X2, wy2 = Y2;
    #pragma unroll
    for (int o = 16; o > 0; o >>= 1) {
        wx1 = fminf(wx1, __shfl_xor_sync(0xffffffffu, wx1, o));
        wy1 = fminf(wy1, __shfl_xor_sync(0xffffffffu, wy1, o));
        wx2 = fmaxf(wx2, __shfl_xor_sync(0xffffffffu, wx2, o));
        wy2 = fmaxf(wy2, __shfl_xor_sync(0xffffffffu, wy2, o));
    }

    // per-lane label screen -> warp-uniform survivor masks
    unsigned msk_lo = (nlabel >= 32) ? 0xffffffffu : ((1u << nlabel) - 1u);
    unsigned msk_hi = (nlabel > 32)  ? ((1u << (nlabel - 32)) - 1u) : 0u;
    bool p0, p1;
    {
        float4 g0 = s_box[lane];
        p0 = (g0.x < wx2) & (g0.z > wx1) & (g0.y < wy2) & (g0.w > wy1);
        int k1 = lane + 32;
        p1 = false;
        if (k1 < KMAX) {
            float4 g1 = s_box[k1];
            p1 = (g1.x < wx2) & (g1.z > wx1) & (g1.y < wy2) & (g1.w > wy1);
        }
    }
    unsigned m0 = __ballot_sync(0xffffffffu, p0) & msk_lo;
    unsigned m1 = __ballot_sync(0xffffffffu, p1) & msk_hi;

    while (m0) {
        int k = __ffs(m0) - 1; m0 &= m0 - 1u;
        const float4 gb = s_box[k];
        const float  th = s_thr[k];
        float iw = fminf(X2, gb.z) - fmaxf(X1, gb.x);
        float ih = fminf(Y2, gb.w) - fmaxf(Y1, gb.y);
        float inter = fmaxf(iw, 0.f) * fmaxf(ih, 0.f);
        MD = fmaxf(MD, inter - th);
    }
    while (m1) {
        int k = __ffs(m1) + 31; m1 &= m1 - 1u;
        const float4 gb = s_box[k];
        const float  th = s_thr[k];
        float iw = fminf(X2, gb.z) - fmaxf(X1, gb.x);
        float ih = fminf(Y2, gb.w) - fmaxf(Y1, gb.y);
        float inter = fmaxf(iw, 0.f) * fmaxf(ih, 0.f);
        MD = fmaxf(MD, inter - th);
    }

    if (active) {
        bool ign = MD > AP;
        bool obj = (s_bits[wid] >> lane) & 1u;
        if ((!ign) || obj)
            f += splus(RC) - (obj ? RC : 0.0f);
    }

    // ---------------- block reduction (deterministic) ------------------------
    // Warp-reduce f; ONLY lane 0 holds the complete warp sum afterwards.
    #pragma unroll
    for (int o = 16; o > 0; o >>= 1) f += __shfl_down_sync(0xffffffffu, f, o);
    if (lane == 0) s_wsum[wid] = d + (double)f;   // d nonzero only at lane 0
    __syncthreads();
    if (t == 0) {
        double s = 0.0;
        #pragma unroll
        for (int w = 0; w < BLK/32; w++) s += s_wsum[w];
        g_partial[blockIdx.y * gridDim.x + blockIdx.x] = s;
        __threadfence();
        int c = atomicAdd(&g_count, 1);
        s_last = (c == TOTB - 1);
    }
    __syncthreads();

    // ---------------- last block: final reduction ----------------------------
    if (s_last) {
        __shared__ double sh[BLK];
        double s = 0.0;
        for (int i = t; i < TOTB; i += BLK) s += g_partial[i];
        sh[t] = s;
        __syncthreads();
        for (int o = BLK/2; o > 0; o >>= 1) {
            if (t < o) sh[t] += sh[t + o];
            __syncthreads();
        }
        if (t == 0) { out[0] = (float)sh[0]; g_count = 0; }
    }
}

extern "C" void kernel_launch(void* const* d_in, const int* in_sizes, int n_in,
                              void* d_out, int out_size) {
    const float* raw     = (const float*)d_in[0];
    const float* labels  = (const float*)d_in[1];
    const float* anchors = (const float*)d_in[2];
    const int*   aidx    = (const int*)d_in[3];
    const int*   imgp    = (const int*)d_in[4];

    dim3 grid(NBLK, NB);
    fused_kernel<<<grid, BLK>>>(raw, labels, anchors, aidx, imgp, (float*)d_out);
}

// round 13
// speedup vs baseline: 1.7457x; 1.1530x over previous
#include <cuda_runtime.h>
#include <stdint.h>

#define NB   16
#define KMAX 50
#define NG   76
#define GG   (NG*NG)      // 5776
#define NA   3
#define NCLS 80
#define NCH  85
#define CELLS (NA*GG)     // 17328
#define BLK  256
#define CPB  BLK          // 256 cells per block (CPT=1)
#define NBLK ((CELLS + BLK - 1)/BLK)  // 68
#define TOTB (NB*NBLK)                // 1088

__device__ double g_partial[TOTB];
__device__ int    g_count;

// bce(sigmoid(x), t) = softplus(x) - t*x   (clamp inactive for |x|<16)
__device__ __forceinline__ float splus(float x) {
    return __logf(1.0f + __expf(x));
}
// sigmoid via single-MUFU hardware tanh: sigm(x) = 0.5*tanh(0.5x) + 0.5
__device__ __forceinline__ float sigm(float x) {
    float y;
    asm("tanh.approx.f32 %0, %1;" : "=f"(y) : "f"(0.5f * x));
    return fmaf(0.5f, y, 0.5f);
}

__global__ void __launch_bounds__(BLK)
fused_kernel(const float* __restrict__ raw,
             const float* __restrict__ labels,
             const float* __restrict__ anchors_all,
             const int*   __restrict__ aidx,
             const int*   __restrict__ imgp,
             float*       __restrict__ out) {
    __shared__ float4   s_box[KMAX];
    __shared__ float    s_thr[KMAX];     // 0.375*area_g
    __shared__ int      s_cell[KMAX];
    __shared__ float    s_t[KMAX][5];    // t0..t3, w2
    __shared__ int      s_cls[KMAX];
    __shared__ float    s_awn[NA], s_ahn[NA];
    __shared__ unsigned s_bits[CPB/32];  // 8 words
    __shared__ int      s_cnt;
    __shared__ double   s_wsum[BLK/32];
    __shared__ int      s_last;

    const int b = blockIdx.y;
    const int t = threadIdx.x;
    const int lane = t & 31, wid = t >> 5;

    // ---------------- prep ---------------------------------------------------
    if (t == 0) s_cnt = 0;
    if (t < CPB/32) s_bits[t] = 0u;
    float img = (float)(*imgp);
    if (t < NA) {
        int ai = aidx[t];
        s_awn[t] = __fdividef(anchors_all[2*ai],     img);
        s_ahn[t] = __fdividef(anchors_all[2*ai + 1], img);
    }
    float lab[5];
    if (t < KMAX) {
        float s = 0.f;
        #pragma unroll
        for (int j = 0; j < 5; j++) { lab[j] = labels[(b*KMAX + t)*5 + j]; s += lab[j]; }
        if (s > 0.f) atomicAdd(&s_cnt, 1);
    }
    __syncthreads();
    const int nlabel = s_cnt;

    if (t < KMAX) {
        bool valid_k = (t < nlabel);
        float tx = lab[1] * (float)NG, ty = lab[2] * (float)NG;
        float tw = lab[3],             th = lab[4];

        int best_all = 0; float best = -1.0f;
        #pragma unroll
        for (int a = 0; a < 9; a++) {
            float aw = __fdividef(anchors_all[2*a], img);
            float ah = __fdividef(anchors_all[2*a+1], img);
            float inter = fminf(tw, aw) * fminf(th, ah);
            float uni   = tw*th + aw*ah - inter;
            float iou   = __fdividef(inter, fmaxf(uni, 1e-16f));
            if (iou > best) { best = iou; best_all = a; }
        }
        bool va = false;
        #pragma unroll
        for (int j = 0; j < NA; j++) va = va || (best_all == aidx[j]);
        int  best_n = best_all % NA;
        int  ti = (int)tx, tj = (int)ty;
        bool valid = valid_k && va && ti >= 0 && ti < NG && tj >= 0 && tj < NG;

        int   cell = -1;
        float t0=0.f,t1=0.f,t2=0.f,t3=0.f,w2=0.f;
        if (valid) {
            cell = (best_n * NG + tj) * NG + ti;
            t0 = tx - floorf(tx);
            t1 = ty - floorf(ty);
            t2 = __logf(__fdividef(tw, s_awn[best_n]) + 1e-16f);
            t3 = __logf(__fdividef(th, s_ahn[best_n]) + 1e-16f);
            w2 = 2.0f - tw * th;
            int local = cell - blockIdx.x * CPB;
            if (local >= 0 && local < CPB)
                atomicOr(&s_bits[local >> 5], 1u << (local & 31));
        }
        float gx=0.f,gy=0.f,gw=0.f,gh=0.f;
        if (valid_k) { gx = tx * (1.0f/(float)NG); gy = ty * (1.0f/(float)NG); gw = tw; gh = th; }

        s_box[t]  = make_float4(gx - gw*0.5f, gy - gh*0.5f, gx + gw*0.5f, gy + gh*0.5f);
        s_thr[t]  = 0.375f * gw * gh;
        s_cell[t] = cell;
        s_t[t][0]=t0; s_t[t][1]=t1; s_t[t][2]=t2; s_t[t][3]=t3; s_t[t][4]=w2;
        s_cls[t]  = (int)lab[0];
    }
    __syncthreads();

    float  f = 0.0f;     // per-thread float accumulator (hot path)
    double d = 0.0;      // obj-epilogue adds (nonzero only at lane 0)

    // ---------------- warp-cooperative obj losses (xy, wh, classes) ---------
    {
        unsigned m = s_bits[wid];
        while (m) {
            int bit = __ffs(m) - 1;
            m &= m - 1u;
            int cellg = blockIdx.x * CPB + wid * 32 + bit;
            int a  = cellg / GG;
            int r  = cellg - a * GG;
            int gy = r / NG, gx = r - gy * NG;

            int winner = 0;
            int b0 = 0, b1 = 0, b2 = 0;
            for (int k = 0; k < nlabel; k++) {
                if (s_cell[k] == cellg) {
                    winner = k;                       // last writer wins
                    int cc = s_cls[k];
                    b0 |= (cc == lane);
                    b1 |= (cc == lane + 32);
                    b2 |= (cc == lane + 64);
                }
            }

            const float* base = raw + ((size_t)((b*NA + a)*NCH))*GG + gy*NG + gx;

            float x0 = base[(5 + lane)      * GG];
            float x1 = base[(5 + lane + 32) * GG];
            float x2 = (lane < 16) ? base[(5 + lane + 64) * GG] : 0.0f;
            float cls_sum = (splus(x0) - (float)b0 * x0)
                          + (splus(x1) - (float)b1 * x1);
            if (lane < 16) cls_sum += splus(x2) - (float)b2 * x2;
            #pragma unroll
            for (int o = 16; o > 0; o >>= 1)
                cls_sum += __shfl_xor_sync(0xffffffffu, cls_sum, o);

            if (lane == 0) {
                float rx = base[0];
                float ry = base[1*GG];
                float rw = base[2*GG];
                float rh = base[3*GG];
                float t0 = s_t[winner][0], t1 = s_t[winner][1];
                float t2 = s_t[winner][2], t3 = s_t[winner][3];
                float w2 = s_t[winner][4];
                float lxy = (splus(rx) - t0*rx) + (splus(ry) - t1*ry);
                float dw = rw - t2, dh = rh - t3;
                d += (double)(cls_sum + w2 * (lxy + 0.5f*(dw*dw + dh*dh)));
            }
        }
    }

    // ---------------- main: screened ignore test + conf loss -----------------
    const int idx = blockIdx.x * BLK + t;
    const bool active = (idx < CELLS);
    float RC = 0.f, X1, Y1, X2, Y2, AP = 0.f, MD = -1e30f;
    {
        int a  = idx / GG;
        int r  = idx - a * GG;
        int gy = r / NG, gx = r - gy * NG;

        if (active) {
            const float* base = raw + ((size_t)((b*NA + a)*NCH))*GG + gy*NG + gx;
            float rx = base[0*GG];
            float ry = base[1*GG];
            float rw = base[2*GG];
            float rh = base[3*GG];
            RC       = base[4*GG];
            const float inv = 1.0f / (float)NG;
            float px = (sigm(rx) + (float)gx) * inv;
            float py = (sigm(ry) + (float)gy) * inv;
            float pw = fminf(__expf(rw) * s_awn[a], 1.0f);
            float ph = fminf(__expf(rh) * s_ahn[a], 1.0f);
            X1 = px - pw*0.5f; Y1 = py - ph*0.5f;
            X2 = px + pw*0.5f; Y2 = py + ph*0.5f;
            AP = 0.375f * pw * ph;
        } else {
            X1 = 1e30f; Y1 = 1e30f; X2 = -1e30f; Y2 = -1e30f;
        }
    }

    // warp-wide conservative bbox (32 adjacent cells)
    float wx1 = X1, wy1 = Y1, wx2 = X2, wy2 = Y2;
    #pragma unroll
    for (int o = 16; o > 0; o >>= 1) {
        wx1 = fminf(wx1, __shfl_xor_sync(0xffffffffu, wx1, o));
        wy1 = fminf(wy1, __shfl_xor_sync(0xffffffffu, wy1, o));
        wx2 = fmaxf(wx2, __shfl_xor_sync(0xffffffffu, wx2, o));
        wy2 = fmaxf(wy2, __shfl_xor_sync(0xffffffffu, wy2, o));
    }

    // per-lane label screen -> warp-uniform survivor masks
    unsigned msk_lo = (nlabel >= 32) ? 0xffffffffu : ((1u << nlabel) - 1u);
    unsigned msk_hi = (nlabel > 32)  ? ((1u << (nlabel - 32)) - 1u) : 0u;
    bool p0, p1;
    {
        float4 g0 = s_box[lane];
        p0 = (g0.x < wx2) & (g0.z > wx1) & (g0.y < wy2) & (g0.w > wy1);
        int k1 = lane + 32;
        p1 = false;
        if (k1 < KMAX) {
            float4 g1 = s_box[k1];
            p1 = (g1.x < wx2) & (g1.z > wx1) & (g1.y < wy2) & (g1.w > wy1);
        }
    }
    unsigned m0 = __ballot_sync(0xffffffffu, p0) & msk_lo;
    unsigned m1 = __ballot_sync(0xffffffffu, p1) & msk_hi;

    while (m0) {
        int k = __ffs(m0) - 1; m0 &= m0 - 1u;
        const float4 gb = s_box[k];
        const float  th = s_thr[k];
        float iw = fminf(X2, gb.z) - fmaxf(X1, gb.x);
        float ih = fminf(Y2, gb.w) - fmaxf(Y1, gb.y);
        float inter = fmaxf(iw, 0.f) * fmaxf(ih, 0.f);
        MD = fmaxf(MD, inter - th);
    }
    while (m1) {
        int k = __ffs(m1) + 31; m1 &= m1 - 1u;
        const float4 gb = s_box[k];
        const float  th = s_thr[k];
        float iw = fminf(X2, gb.z) - fmaxf(X1, gb.x);
        float ih = fminf(Y2, gb.w) - fmaxf(Y1, gb.y);
        float inter = fmaxf(iw, 0.f) * fmaxf(ih, 0.f);
        MD = fmaxf(MD, inter - th);
    }

    if (active) {
        bool ign = MD > AP;
        bool obj = (s_bits[wid] >> lane) & 1u;
        if ((!ign) || obj)
            f += splus(RC) - (obj ? RC : 0.0f);
    }

    // ---------------- block reduction (deterministic) ------------------------
    #pragma unroll
    for (int o = 16; o > 0; o >>= 1) f += __shfl_down_sync(0xffffffffu, f, o);
    if (lane == 0) s_wsum[wid] = d + (double)f;   // d nonzero only at lane 0
    __syncthreads();
    if (t == 0) {
        double s = 0.0;
        #pragma unroll
        for (int w = 0; w < BLK/32; w++) s += s_wsum[w];
        g_partial[blockIdx.y * gridDim.x + blockIdx.x] = s;
        __threadfence();
        int c = atomicAdd(&g_count, 1);
        s_last = (c == TOTB - 1);
    }
    __syncthreads();

    // ---------------- last block: final reduction ----------------------------
    if (s_last) {
        __shared__ double sh[BLK];
        double s = 0.0;
        for (int i = t; i < TOTB; i += BLK) s += g_partial[i];
        sh[t] = s;
        __syncthreads();
        for (int o = BLK/2; o > 0; o >>= 1) {
            if (t < o) sh[t] += sh[t + o];
            __syncthreads();
        }
        if (t == 0) { out[0] = (float)sh[0]; g_count = 0; }
    }
}

extern "C" void kernel_launch(void* const* d_in, const int* in_sizes, int n_in,
                              void* d_out, int out_size) {
    const float* raw     = (const float*)d_in[0];
    const float* labels  = (const float*)d_in[1];
    const float* anchors = (const float*)d_in[2];
    const int*   aidx    = (const int*)d_in[3];
    const int*   imgp    = (const int*)d_in[4];

    dim3 grid(NBLK, NB);
    fused_kernel<<<grid, BLK>>>(raw, labels, anchors, aidx, imgp, (float*)d_out);
}